// round 4
// baseline (speedup 1.0000x reference)
#include <cuda_runtime.h>
#include <math.h>
#include <float.h>
#include <stdint.h>

// ---------------- problem constants ----------------
#define N_X    2048
#define M_BUF  131072
#define D_DIM  64
#define KK     11                 // keep K+1 smallest
#define SPLITS 18
#define TPS    57                 // tiles per split (last split gets 55)
#define TILES_TOTAL (M_BUF / 128) // 1024
#define BX     64                 // x rows per CTA
#define QS     31.75f             // int8 quantization scale

// ---------------- device scratch ----------------
__device__ char g_xq8[N_X * D_DIM];
__device__ char g_bq8[(size_t)M_BUF * D_DIM];
__device__ int  g_bn2i[M_BUF];
__device__ unsigned g_cand[(size_t)N_X * SPLITS * KK];

// ---------------- helpers ----------------
__device__ __forceinline__ uint32_t smem_u32(const void* p) {
    uint32_t a;
    asm("{ .reg .u64 t; cvta.to.shared.u64 t, %1; cvt.u32.u64 %0, t; }" : "=r"(a) : "l"(p));
    return a;
}
#define CP_ASYNC16(ds, gp) asm volatile("cp.async.cg.shared.global [%0], [%1], 16;" :: "r"(ds), "l"(gp))
#define CP_ASYNC8(ds, gp)  asm volatile("cp.async.ca.shared.global [%0], [%1], 8;"  :: "r"(ds), "l"(gp))
#define CP_COMMIT() asm volatile("cp.async.commit_group;" ::: "memory")
#define CP_WAIT(n)  asm volatile("cp.async.wait_group %0;" :: "n"(n) : "memory")

// ---------------- kernel 1: quantize to int8 + int squared norms ----------------
__global__ void prep_kernel(const float* __restrict__ x, const float* __restrict__ buf) {
    int gw = (blockIdx.x * blockDim.x + threadIdx.x) >> 5;
    int lane = threadIdx.x & 31;
    if (gw >= M_BUF + N_X) return;
    const float* src;
    char* dst;
    bool is_buf = (gw < M_BUF);
    if (is_buf) { src = buf + (size_t)gw * D_DIM; dst = g_bq8 + (size_t)gw * D_DIM; }
    else { int r = gw - M_BUF; src = x + (size_t)r * D_DIM; dst = g_xq8 + (size_t)r * D_DIM; }
    float2 v = reinterpret_cast<const float2*>(src)[lane];
    int q0 = __float2int_rn(v.x * QS); q0 = max(-127, min(127, q0));
    int q1 = __float2int_rn(v.y * QS); q1 = max(-127, min(127, q1));
    unsigned short pk = (unsigned short)((q0 & 0xFF) | ((q1 & 0xFF) << 8));
    reinterpret_cast<unsigned short*>(dst)[lane] = pk;
    int s = q0 * q0 + q1 * q1;
    #pragma unroll
    for (int o = 16; o > 0; o >>= 1) s += __shfl_xor_sync(0xffffffffu, s, o);
    if (is_buf && lane == 0) g_bn2i[gw] = s;
}

// ---------------- kernel 2: dp4a distance + fused int top-11 ----------------
// smem layout (bytes): XS [0,4096); B0 [4096,13312) 128x72; B1 [13312,22528);
// BN0 [22528,23040); BN1 [23040,23552). Merge aliases [0,45056) afterwards.
#define XS_OFF  0
#define B0_OFF  4096
#define B1_OFF  13312
#define BN0_OFF 22528
#define BN1_OFF 23040
#define ROWB    72
#define SMEM_TOTAL 46080

extern __shared__ unsigned char smem_raw[];

__device__ __forceinline__ void prefetch_tile(uint32_t sb, int tile, int sel, int tid) {
    uint32_t boff = sel ? B1_OFF : B0_OFF;
    const char* gbase = g_bq8 + (size_t)tile * 128 * D_DIM;
    #pragma unroll
    for (int ii = 0; ii < 4; ii++) {
        int q = tid + 256 * ii;             // 1024 8-byte chunks
        int row = q >> 3, o = q & 7;
        CP_ASYNC8(sb + boff + row * ROWB + o * 8, gbase + (size_t)row * D_DIM + o * 8);
    }
    if (tid < 32) {
        uint32_t bnoff = sel ? BN1_OFF : BN0_OFF;
        CP_ASYNC16(sb + bnoff + tid * 16, (const char*)(g_bn2i + tile * 128) + tid * 16);
    }
}

__global__ void __launch_bounds__(256)
pbe_dp4a() {
    const int tid = threadIdx.x;
    const int i = tid >> 4;                 // 0..15: x rows {i, i+16, i+32, i+48}
    const int j = tid & 15;                 // 0..15: buf cols {j + 16n, n=0..7}
    const int xblock = blockIdx.x * BX;
    const int split  = blockIdx.y;
    const int tbeg = split * TPS;
    const int tend = min(tbeg + TPS, TILES_TOTAL);

    uint32_t sb = smem_u32(smem_raw);

    // x tile: 64 rows x 64B
    {
        int row = tid >> 2, q = tid & 3;
        CP_ASYNC16(sb + XS_OFF + row * 64 + q * 16,
                   g_xq8 + (size_t)(xblock + row) * D_DIM + q * 16);
    }
    prefetch_tile(sb, tbeg, 0, tid);
    CP_COMMIT();

    // per-(thread, x-row) running top-11 of packed (key<<13 | loc)
    unsigned tk[4][KK];
    int thrRaw[4], mxi[4];
    #pragma unroll
    for (int a = 0; a < 4; a++) {
        #pragma unroll
        for (int k = 0; k < KK; k++) tk[a][k] = 0xFFFFFFFFu;
        thrRaw[a] = INT32_MAX; mxi[a] = 0;
    }

    for (int t = tbeg; t < tend; t++) {
        const int tl = t - tbeg;
        const int st = tl & 1;
        if (t + 1 < tend) {
            prefetch_tile(sb, t + 1, st ^ 1, tid);
            CP_COMMIT();
            CP_WAIT(1);
        } else {
            CP_WAIT(0);
        }
        __syncthreads();

        const unsigned char* bt = smem_raw + (st ? B1_OFF : B0_OFF);
        const int* bnp = (const int*)(smem_raw + (st ? BN1_OFF : BN0_OFF));

        int bnv[8];
        #pragma unroll
        for (int n = 0; n < 8; n++) bnv[n] = bnp[j + n * 16];

        int acc[4][8];
        #pragma unroll
        for (int a = 0; a < 4; a++)
            #pragma unroll
            for (int n = 0; n < 8; n++) acc[a][n] = 0;

        #pragma unroll
        for (int cp = 0; cp < 8; cp++) {
            uint64_t xw[4], bw[8];
            #pragma unroll
            for (int a = 0; a < 4; a++)
                xw[a] = *(const uint64_t*)(smem_raw + XS_OFF + (i + a * 16) * 64 + cp * 8);
            #pragma unroll
            for (int n = 0; n < 8; n++)
                bw[n] = *(const uint64_t*)(bt + (j + n * 16) * ROWB + cp * 8);
            #pragma unroll
            for (int a = 0; a < 4; a++)
                #pragma unroll
                for (int n = 0; n < 8; n++) {
                    acc[a][n] = __dp4a((int)(unsigned)xw[a], (int)(unsigned)bw[n], acc[a][n]);
                    acc[a][n] = __dp4a((int)(xw[a] >> 32), (int)(bw[n] >> 32), acc[a][n]);
                }
        }

        // epilogue: key = bn - 2*dot (per-row ordering == d2 ordering)
        #pragma unroll
        for (int a = 0; a < 4; a++) {
            #pragma unroll
            for (int n = 0; n < 8; n++) {
                int key = bnv[n] - 2 * acc[a][n];
                if (key < thrRaw[a]) {
                    int kc = key + 131072;
                    kc = max(kc, 0); kc = min(kc, 262143);
                    unsigned loc = (unsigned)(tl * 128 + j + n * 16);
                    tk[a][mxi[a]] = ((unsigned)kc << 13) | loc;
                    unsigned m = tk[a][0]; int mi = 0;
                    #pragma unroll
                    for (int k = 1; k < KK; k++)
                        if (tk[a][k] > m) { m = tk[a][k]; mi = k; }
                    thrRaw[a] = (int)(m >> 13) - 131072; mxi[a] = mi;
                }
            }
        }
        __syncthreads();
    }

    // block merge: 16 j-threads per row -> exact per-(row,split) top-11
    unsigned* csh = (unsigned*)smem_raw;    // [64][16][11]
    #pragma unroll
    for (int a = 0; a < 4; a++) {
        int base = ((i + a * 16) * 16 + j) * KK;
        #pragma unroll
        for (int k = 0; k < KK; k++) csh[base + k] = tk[a][k];
    }
    __syncthreads();

    if (tid < BX) {
        const unsigned* src = csh + tid * (16 * KK);
        unsigned best[KK];
        unsigned thrv = 0xFFFFFFFFu; int mi = 0;
        #pragma unroll
        for (int k = 0; k < KK; k++) best[k] = 0xFFFFFFFFu;
        for (int s = 0; s < 16 * KK; s++) {
            unsigned v = src[s];
            if (v < thrv) {
                best[mi] = v;
                unsigned m = best[0]; int mj = 0;
                #pragma unroll
                for (int q = 1; q < KK; q++)
                    if (best[q] > m) { m = best[q]; mj = q; }
                thrv = m; mi = mj;
            }
        }
        unsigned* dst = g_cand + ((size_t)(xblock + tid) * SPLITS + split) * KK;
        #pragma unroll
        for (int k = 0; k < KK; k++) dst[k] = best[k];
    }
}

// ---------------- kernel 3: exact fp32 recompute + final reduction ----------------
__global__ void __launch_bounds__(256)
finalize_kernel(const float* __restrict__ x, const float* __restrict__ buf,
                float* __restrict__ out) {
    const int row = blockIdx.x;
    const int tid = threadIdx.x;
    __shared__ float4 xr[16];
    __shared__ float sd2[SPLITS * KK];

    if (tid < 16)
        xr[tid] = reinterpret_cast<const float4*>(x + (size_t)row * D_DIM)[tid];
    __syncthreads();

    if (tid < SPLITS * KK) {
        unsigned cand = g_cand[(size_t)row * SPLITS * KK + tid];
        int split = tid / KK;
        int loc = (int)(cand & 8191u);
        long gidx = (long)split * (TPS * 128) + loc;
        if (gidx >= M_BUF) gidx = M_BUF - 1;    // safety clamp (unreachable)
        const float4* b4 = reinterpret_cast<const float4*>(buf + gidx * D_DIM);
        float s = 0.f;
        #pragma unroll
        for (int q = 0; q < 16; q++) {
            float4 bv = b4[q], xv = xr[q];
            float d0 = xv.x - bv.x, d1 = xv.y - bv.y;
            float d2 = xv.z - bv.z, d3 = xv.w - bv.w;
            s += d0 * d0 + d1 * d1 + d2 * d2 + d3 * d3;
        }
        sd2[tid] = s;
    }
    __syncthreads();

    if (tid == 0) {
        float best[KK];
        float thrv = FLT_MAX; int mi = 0;
        #pragma unroll
        for (int k = 0; k < KK; k++) best[k] = FLT_MAX;
        for (int s = 0; s < SPLITS * KK; s++) {
            float v = sd2[s];
            if (v < thrv) {
                best[mi] = v;
                float m = best[0]; int mj = 0;
                #pragma unroll
                for (int q = 1; q < KK; q++)
                    if (best[q] > m) { m = best[q]; mj = q; }
                thrv = m; mi = mj;
            }
        }
        float ssum = 0.f, rmin = FLT_MAX;
        #pragma unroll
        for (int k = 0; k < KK; k++) {
            float r = sqrtf(best[k]);
            ssum += r;
            rmin = fminf(rmin, r);
        }
        out[row] = log1pf((ssum - rmin) * 0.1f);  // drop self, mean of 10
    }
}

// ---------------------------------------------------------------------------
extern "C" void kernel_launch(void* const* d_in, const int* in_sizes, int n_in,
                              void* d_out, int out_size) {
    const float* x   = (const float*)d_in[0];
    const float* buf = (const float*)d_in[1];
    if (n_in >= 2 && in_sizes[0] != N_X * D_DIM) {
        const float* t = x; x = buf; buf = t;
    }

    int total_warps = M_BUF + N_X;
    prep_kernel<<<(total_warps * 32 + 255) / 256, 256>>>(x, buf);
    pbe_dp4a<<<dim3(N_X / BX, SPLITS), 256, SMEM_TOTAL>>>();
    finalize_kernel<<<N_X, 256>>>(x, buf, (float*)d_out);
}

// round 6
// speedup vs baseline: 1.3675x; 1.3675x over previous
#include <cuda_runtime.h>
#include <cuda_fp16.h>
#include <math.h>
#include <float.h>
#include <stdint.h>

// ---------------- problem constants ----------------
#define N_X    2048
#define M_BUF  131072
#define D_DIM  64
#define KK     11                 // keep K+1 smallest
#define SPLITS 18
#define TPS    57                 // tiles per split (last split: 55)
#define TILES_TOTAL (M_BUF / 128) // 1024
#define BX     64                 // x rows per CTA

// ---------------- device scratch ----------------
// buf pair-interleaved: g_bp[p*64 + k] = half2(buf[2p][k], buf[2p+1][k])
__device__ __half2 g_bp[(size_t)(M_BUF / 2) * D_DIM];
// x duplicated: g_xd[r*64 + k] = half2(x[r][k], x[r][k])
__device__ __half2 g_xd[(size_t)N_X * D_DIM];
// buf norms pair-packed: g_bnp[p] = half2(bn2[2p], bn2[2p+1])
__device__ __half2 g_bnp[M_BUF / 2];
__device__ unsigned g_cand[(size_t)N_X * SPLITS * KK];

// ---------------- helpers ----------------
__device__ __forceinline__ uint32_t smem_u32(const void* p) {
    uint32_t a;
    asm("{ .reg .u64 t; cvta.to.shared.u64 t, %1; cvt.u32.u64 %0, t; }" : "=r"(a) : "l"(p));
    return a;
}
#define CP_ASYNC16(ds, gp) asm volatile("cp.async.cg.shared.global [%0], [%1], 16;" :: "r"(ds), "l"(gp))
#define CP_COMMIT() asm volatile("cp.async.commit_group;" ::: "memory")
#define CP_WAIT(n)  asm volatile("cp.async.wait_group %0;" :: "n"(n) : "memory")

__device__ __forceinline__ __half2 asH2(unsigned u) { return *reinterpret_cast<__half2*>(&u); }

// sorted ascending insert: assumes v < tk[10]; all indices constant -> registers
__device__ __forceinline__ void bubble11(unsigned tk[KK], unsigned v) {
    tk[10] = v;
    #pragma unroll
    for (int s = 10; s >= 1; s--) {
        unsigned lo = min(tk[s - 1], tk[s]);
        unsigned hi = max(tk[s - 1], tk[s]);
        tk[s - 1] = lo; tk[s] = hi;
    }
}

// ---------------- kernel 1: fp32 -> fp16 pair-interleave + pair norms ----------
__global__ void prep_kernel(const float* __restrict__ x, const float* __restrict__ buf) {
    int gw = (blockIdx.x * blockDim.x + threadIdx.x) >> 5;   // warp id
    int lane = threadIdx.x & 31;
    const int NPAIR = M_BUF / 2;
    if (gw >= NPAIR + N_X) return;
    if (gw < NPAIR) {
        // one warp handles buf rows 2p and 2p+1
        const float2 v0 = reinterpret_cast<const float2*>(buf + (size_t)(2 * gw) * D_DIM)[lane];
        const float2 v1 = reinterpret_cast<const float2*>(buf + (size_t)(2 * gw + 1) * D_DIM)[lane];
        __half2* dst = g_bp + (size_t)gw * D_DIM;
        dst[2 * lane]     = __floats2half2_rn(v0.x, v1.x);
        dst[2 * lane + 1] = __floats2half2_rn(v0.y, v1.y);
        float s0 = v0.x * v0.x + v0.y * v0.y;
        float s1 = v1.x * v1.x + v1.y * v1.y;
        #pragma unroll
        for (int o = 16; o > 0; o >>= 1) {
            s0 += __shfl_xor_sync(0xffffffffu, s0, o);
            s1 += __shfl_xor_sync(0xffffffffu, s1, o);
        }
        if (lane == 0) g_bnp[gw] = __floats2half2_rn(s0, s1);
    } else {
        int r = gw - NPAIR;
        const float2 v = reinterpret_cast<const float2*>(x + (size_t)r * D_DIM)[lane];
        __half2* dst = g_xd + (size_t)r * D_DIM;
        dst[2 * lane]     = __floats2half2_rn(v.x, v.x);
        dst[2 * lane + 1] = __floats2half2_rn(v.y, v.y);
    }
}

// ---------------- kernel 2: HFMA2 distance + register top-11 ----------------
// smem: XS [0,16384) 64 rows x 256B; B0 [16384,+17408) 64 pairs x 272B (pad);
// B1 [33792,+17408); BN0 @51200 (256B); BN1 @51456. total 51712.
// merge phase aliases [0,45056) as u32[64][16][11].
#define XS_OFF  0
#define B0_OFF  16384
#define B1_OFF  33792
#define BN0_OFF 51200
#define BN1_OFF 51456
#define PROWB   272
#define SMEM_TOTAL 51712

extern __shared__ unsigned char smem_raw[];

__device__ __forceinline__ void prefetch_tile(uint32_t sb, int tile, int sel, int tid) {
    uint32_t boff = sel ? B1_OFF : B0_OFF;
    const char* src = (const char*)g_bp + (size_t)tile * 16384;
    #pragma unroll
    for (int ii = 0; ii < 4; ii++) {
        int q = tid + 256 * ii;            // 1024 16B chunks
        int prow = q >> 4, c = q & 15;
        CP_ASYNC16(sb + boff + prow * PROWB + c * 16, src + prow * 256 + c * 16);
    }
    if (tid < 16) {
        uint32_t bnoff = sel ? BN1_OFF : BN0_OFF;
        CP_ASYNC16(sb + bnoff + tid * 16, (const char*)g_bnp + (size_t)tile * 256 + tid * 16);
    }
}

__global__ void __launch_bounds__(256, 2)
pbe_h2() {
    const int tid = threadIdx.x;
    const int i = tid >> 4;                // x rows {i, i+16, i+32, i+48}
    const int j = tid & 15;                // pairs  {j, j+16, j+32, j+48}
    const int xblock = blockIdx.x * BX;
    const int split  = blockIdx.y;
    const int tbeg = split * TPS;
    const int tend = min(tbeg + TPS, TILES_TOTAL);

    uint32_t sb = smem_u32(smem_raw);

    // x tile: linear 16KB copy from g_xd
    {
        const char* src = (const char*)g_xd + (size_t)xblock * 256;
        #pragma unroll
        for (int ii = 0; ii < 4; ii++) {
            int q = tid + 256 * ii;
            CP_ASYNC16(sb + XS_OFF + q * 16, src + q * 16);
        }
    }
    prefetch_tile(sb, tbeg, 0, tid);
    CP_COMMIT();

    unsigned tk[4][KK];
    #pragma unroll
    for (int a = 0; a < 4; a++)
        #pragma unroll
        for (int k = 0; k < KK; k++) tk[a][k] = 0xFFFFFFFFu;

    const __half2 m2 = __float2half2_rn(-2.0f);

    for (int t = tbeg; t < tend; t++) {
        const int tl = t - tbeg;
        const int st = tl & 1;
        if (t + 1 < tend) {
            prefetch_tile(sb, t + 1, st ^ 1, tid);
            CP_COMMIT();
            CP_WAIT(1);
        } else {
            CP_WAIT(0);
        }
        __syncthreads();

        const unsigned char* bt = smem_raw + (st ? B1_OFF : B0_OFF);
        const __half2* bnp = (const __half2*)(smem_raw + (st ? BN1_OFF : BN0_OFF));

        __half2 bn2p[4];
        #pragma unroll
        for (int p = 0; p < 4; p++) bn2p[p] = bnp[j + p * 16];

        __half2 acc[4][4];
        #pragma unroll
        for (int a = 0; a < 4; a++)
            #pragma unroll
            for (int p = 0; p < 4; p++) acc[a][p] = __float2half2_rn(0.f);

        #pragma unroll
        for (int cp = 0; cp < 16; cp++) {
            uint4 xw[4], bw[4];
            #pragma unroll
            for (int a = 0; a < 4; a++)
                xw[a] = *(const uint4*)(smem_raw + XS_OFF + (i + a * 16) * 256 + cp * 16);
            #pragma unroll
            for (int p = 0; p < 4; p++)
                bw[p] = *(const uint4*)(bt + (j + p * 16) * PROWB + cp * 16);
            #pragma unroll
            for (int a = 0; a < 4; a++)
                #pragma unroll
                for (int p = 0; p < 4; p++) {
                    acc[a][p] = __hfma2(asH2(xw[a].x), asH2(bw[p].x), acc[a][p]);
                    acc[a][p] = __hfma2(asH2(xw[a].y), asH2(bw[p].y), acc[a][p]);
                    acc[a][p] = __hfma2(asH2(xw[a].z), asH2(bw[p].z), acc[a][p]);
                    acc[a][p] = __hfma2(asH2(xw[a].w), asH2(bw[p].w), acc[a][p]);
                }
        }

        // epilogue: key = bn2 - 2*dot ; pack (biased float bits | loc) ; top-11
        #pragma unroll
        for (int a = 0; a < 4; a++) {
            #pragma unroll
            for (int p = 0; p < 4; p++) {
                __half2 key2 = __hfma2(m2, acc[a][p], bn2p[p]);
                float2 kf = __half22float2(key2);
                unsigned loc = (unsigned)(tl * 128 + (j + p * 16) * 2);
                unsigned u0 = (__float_as_uint(kf.x + 192.0f) & 0xFFFFE000u) | loc;
                unsigned u1 = (__float_as_uint(kf.y + 192.0f) & 0xFFFFE000u) | (loc + 1);
                if (u0 < tk[a][10]) bubble11(tk[a], u0);
                if (u1 < tk[a][10]) bubble11(tk[a], u1);
            }
        }
        __syncthreads();
    }

    // block merge: 16 j-threads per row -> per-(row,split) top-11
    unsigned* csh = (unsigned*)smem_raw;   // [64][16][11]
    #pragma unroll
    for (int a = 0; a < 4; a++) {
        int base = ((i + a * 16) * 16 + j) * KK;
        #pragma unroll
        for (int k = 0; k < KK; k++) csh[base + k] = tk[a][k];
    }
    __syncthreads();

    if (tid < BX) {
        const unsigned* src = csh + tid * (16 * KK);
        unsigned best[KK];
        #pragma unroll
        for (int k = 0; k < KK; k++) best[k] = 0xFFFFFFFFu;
        for (int s = 0; s < 16 * KK; s++) {
            unsigned v = src[s];
            if (v < best[10]) bubble11(best, v);
        }
        unsigned* dst = g_cand + ((size_t)(xblock + tid) * SPLITS + split) * KK;
        #pragma unroll
        for (int k = 0; k < KK; k++) dst[k] = best[k];
    }
}

// ---------------- kernel 3: exact fp32 recompute + final reduction ----------
__global__ void __launch_bounds__(256)
finalize_kernel(const float* __restrict__ x, const float* __restrict__ buf,
                float* __restrict__ out) {
    const int row = blockIdx.x;
    const int tid = threadIdx.x;
    __shared__ float4 xr[16];
    __shared__ float sd2[SPLITS * KK];

    if (tid < 16)
        xr[tid] = reinterpret_cast<const float4*>(x + (size_t)row * D_DIM)[tid];
    __syncthreads();

    if (tid < SPLITS * KK) {
        unsigned cand = g_cand[(size_t)row * SPLITS * KK + tid];
        int split = tid / KK;
        int loc = (int)(cand & 0x1FFFu);
        long gidx = (long)split * (TPS * 128) + loc;
        if (gidx >= M_BUF) gidx = M_BUF - 1;   // safety (unreachable)
        const float4* b4 = reinterpret_cast<const float4*>(buf + gidx * D_DIM);
        float s = 0.f;
        #pragma unroll
        for (int q = 0; q < 16; q++) {
            float4 bv = b4[q], xv = xr[q];
            float d0 = xv.x - bv.x, d1 = xv.y - bv.y;
            float d2 = xv.z - bv.z, d3 = xv.w - bv.w;
            s += d0 * d0 + d1 * d1 + d2 * d2 + d3 * d3;
        }
        sd2[tid] = s;
    }
    __syncthreads();

    if (tid == 0) {
        float best[KK];
        float thrv = FLT_MAX; int mi = 0;
        #pragma unroll
        for (int k = 0; k < KK; k++) best[k] = FLT_MAX;
        for (int s = 0; s < SPLITS * KK; s++) {
            float v = sd2[s];
            if (v < thrv) {
                best[mi] = v;
                float m = best[0]; int mj = 0;
                #pragma unroll
                for (int q = 1; q < KK; q++)
                    if (best[q] > m) { m = best[q]; mj = q; }
                thrv = m; mi = mj;
            }
        }
        float ssum = 0.f, rmin = FLT_MAX;
        #pragma unroll
        for (int k = 0; k < KK; k++) {
            float r = sqrtf(best[k]);
            ssum += r;
            rmin = fminf(rmin, r);
        }
        out[row] = log1pf((ssum - rmin) * 0.1f);   // drop self-match, mean of 10
    }
}

// ---------------------------------------------------------------------------
extern "C" void kernel_launch(void* const* d_in, const int* in_sizes, int n_in,
                              void* d_out, int out_size) {
    const float* x   = (const float*)d_in[0];
    const float* buf = (const float*)d_in[1];
    if (n_in >= 2 && in_sizes[0] != N_X * D_DIM) {
        const float* t = x; x = buf; buf = t;
    }

    cudaFuncSetAttribute(pbe_h2, cudaFuncAttributeMaxDynamicSharedMemorySize, SMEM_TOTAL);

    int total_warps = M_BUF / 2 + N_X;     // pair warps + x warps
    prep_kernel<<<(total_warps * 32 + 255) / 256, 256>>>(x, buf);
    pbe_h2<<<dim3(N_X / BX, SPLITS), 256, SMEM_TOTAL>>>();
    finalize_kernel<<<N_X, 256>>>(x, buf, (float*)d_out);
}

// round 7
// speedup vs baseline: 1.4900x; 1.0895x over previous
#include <cuda_runtime.h>
#include <cuda_fp16.h>
#include <math.h>
#include <float.h>
#include <stdint.h>

// ---------------- problem constants ----------------
#define N_X    2048
#define M_BUF  131072
#define D_DIM  64
#define KK     11                 // keep K+1 smallest
#define SPLITS 9
#define TPS    114                // tiles per split (last split: 112)
#define TILES_TOTAL (M_BUF / 128) // 1024
#define BX     64                 // x rows per CTA
#define KBIAS  128.0f             // key bias so biased keys are positive halfs

// ---------------- device scratch ----------------
// buf pair-interleaved: g_bp[p*64 + k] = half2(buf[2p][k], buf[2p+1][k])
__device__ __half2 g_bp[(size_t)(M_BUF / 2) * D_DIM];
// x duplicated: g_xd[r*64 + k] = half2(x[r][k], x[r][k])
__device__ __half2 g_xd[(size_t)N_X * D_DIM];
// biased pair norms: g_bnp[p] = half2(bn2[2p]+128, bn2[2p+1]+128)
__device__ __half2 g_bnp[M_BUF / 2];
__device__ unsigned g_cand[(size_t)N_X * SPLITS * KK];

// ---------------- helpers ----------------
__device__ __forceinline__ uint32_t smem_u32(const void* p) {
    uint32_t a;
    asm("{ .reg .u64 t; cvta.to.shared.u64 t, %1; cvt.u32.u64 %0, t; }" : "=r"(a) : "l"(p));
    return a;
}
#define CP_ASYNC16(ds, gp) asm volatile("cp.async.cg.shared.global [%0], [%1], 16;" :: "r"(ds), "l"(gp))
#define CP_COMMIT() asm volatile("cp.async.commit_group;" ::: "memory")
#define CP_WAIT(n)  asm volatile("cp.async.wait_group %0;" :: "n"(n) : "memory")

__device__ __forceinline__ __half2 asH2(unsigned u) { return *reinterpret_cast<__half2*>(&u); }

// sorted ascending insert: caller guarantees v < tk[10]; constant indices -> regs
__device__ __forceinline__ void bubble11(unsigned tk[KK], unsigned v) {
    tk[10] = v;
    #pragma unroll
    for (int s = 10; s >= 1; s--) {
        unsigned lo = min(tk[s - 1], tk[s]);
        unsigned hi = max(tk[s - 1], tk[s]);
        tk[s - 1] = lo; tk[s] = hi;
    }
}

// ---------------- kernel 1: fp16 pack + biased pair norms ----------------
__global__ void prep_kernel(const float* __restrict__ x, const float* __restrict__ buf) {
    int gw = (blockIdx.x * blockDim.x + threadIdx.x) >> 5;
    int lane = threadIdx.x & 31;
    const int NPAIR = M_BUF / 2;
    if (gw >= NPAIR + N_X) return;
    if (gw < NPAIR) {
        const float2 v0 = reinterpret_cast<const float2*>(buf + (size_t)(2 * gw) * D_DIM)[lane];
        const float2 v1 = reinterpret_cast<const float2*>(buf + (size_t)(2 * gw + 1) * D_DIM)[lane];
        __half2* dst = g_bp + (size_t)gw * D_DIM;
        dst[2 * lane]     = __floats2half2_rn(v0.x, v1.x);
        dst[2 * lane + 1] = __floats2half2_rn(v0.y, v1.y);
        float s0 = v0.x * v0.x + v0.y * v0.y;
        float s1 = v1.x * v1.x + v1.y * v1.y;
        #pragma unroll
        for (int o = 16; o > 0; o >>= 1) {
            s0 += __shfl_xor_sync(0xffffffffu, s0, o);
            s1 += __shfl_xor_sync(0xffffffffu, s1, o);
        }
        if (lane == 0) g_bnp[gw] = __floats2half2_rn(s0 + KBIAS, s1 + KBIAS);
    } else {
        int r = gw - NPAIR;
        const float2 v = reinterpret_cast<const float2*>(x + (size_t)r * D_DIM)[lane];
        __half2* dst = g_xd + (size_t)r * D_DIM;
        dst[2 * lane]     = __floats2half2_rn(v.x, v.x);
        dst[2 * lane + 1] = __floats2half2_rn(v.y, v.y);
    }
}

// ---------------- kernel 2: HFMA2 distances + register top-11 ----------------
// smem: XS [0,16384); B0/B1/B2 @16384+17408*s (64 pairs x 272B);
// BN0/1/2 @68608+256*s. total 69632. merge phase aliases [0,45056).
#define XS_OFF  0
#define BB_OFF  16384
#define BB_STRIDE 17408
#define BN_OFF  68608
#define PROWB   272
#define SMEM_TOTAL 69632

extern __shared__ unsigned char smem_raw[];

__device__ __forceinline__ void prefetch_tile(uint32_t sb, int tile, int sel, int tid) {
    uint32_t boff = BB_OFF + sel * BB_STRIDE;
    const char* src = (const char*)g_bp + (size_t)tile * 16384;
    #pragma unroll
    for (int ii = 0; ii < 4; ii++) {
        int q = tid + 256 * ii;            // 1024 16B chunks
        int prow = q >> 4, c = q & 15;
        CP_ASYNC16(sb + boff + prow * PROWB + c * 16, src + prow * 256 + c * 16);
    }
    if (tid < 16)
        CP_ASYNC16(sb + BN_OFF + sel * 256 + tid * 16,
                   (const char*)g_bnp + (size_t)tile * 256 + tid * 16);
}

__global__ void __launch_bounds__(256, 2)
pbe_h2() {
    const int tid = threadIdx.x;
    const int i = tid >> 4;                // x rows {i, i+16, i+32, i+48}
    const int j = tid & 15;                // pairs  {j, j+16, j+32, j+48}
    const int xblock = blockIdx.x * BX;
    const int split  = blockIdx.y;
    const int tbeg = split * TPS;
    const int tend = min(tbeg + TPS, TILES_TOTAL);

    uint32_t sb = smem_u32(smem_raw);

    // x tile: linear 16KB copy from g_xd
    {
        const char* src = (const char*)g_xd + (size_t)xblock * 256;
        #pragma unroll
        for (int ii = 0; ii < 4; ii++) {
            int q = tid + 256 * ii;
            CP_ASYNC16(sb + XS_OFF + q * 16, src + q * 16);
        }
    }
    prefetch_tile(sb, tbeg, 0, tid);
    CP_COMMIT();
    prefetch_tile(sb, tbeg + 1, 1, tid);
    CP_COMMIT();

    unsigned tk[4][KK];
    #pragma unroll
    for (int a = 0; a < 4; a++)
        #pragma unroll
        for (int k = 0; k < KK; k++) tk[a][k] = 0xFFFFFFFFu;

    const __half2 m2 = __float2half2_rn(-2.0f);

    int s_cur = 0;
    for (int t = tbeg; t < tend; t++) {
        const int tl = t - tbeg;
        CP_WAIT(1);                        // tile t resident
        __syncthreads();                   // also: all warps done reading buf s_cur (from t-3)
        {
            int s_nxt = s_cur + 2; if (s_nxt >= 3) s_nxt -= 3;
            if (t + 2 < tend) prefetch_tile(sb, t + 2, s_nxt, tid);
            CP_COMMIT();
        }

        const unsigned char* bt = smem_raw + BB_OFF + s_cur * BB_STRIDE;
        const __half2* bnp = (const __half2*)(smem_raw + BN_OFF + s_cur * 256);

        __half2 bnb[4];
        #pragma unroll
        for (int p = 0; p < 4; p++) bnb[p] = bnp[j + p * 16];

        __half2 acc[4][4];
        #pragma unroll
        for (int a = 0; a < 4; a++)
            #pragma unroll
            for (int p = 0; p < 4; p++) acc[a][p] = __float2half2_rn(0.f);

        #pragma unroll
        for (int cp = 0; cp < 16; cp++) {
            uint4 xw[4], bw[4];
            #pragma unroll
            for (int a = 0; a < 4; a++)
                xw[a] = *(const uint4*)(smem_raw + XS_OFF + (i + a * 16) * 256 + cp * 16);
            #pragma unroll
            for (int p = 0; p < 4; p++)
                bw[p] = *(const uint4*)(bt + (j + p * 16) * PROWB + cp * 16);
            #pragma unroll
            for (int a = 0; a < 4; a++)
                #pragma unroll
                for (int p = 0; p < 4; p++) {
                    acc[a][p] = __hfma2(asH2(xw[a].x), asH2(bw[p].x), acc[a][p]);
                    acc[a][p] = __hfma2(asH2(xw[a].y), asH2(bw[p].y), acc[a][p]);
                    acc[a][p] = __hfma2(asH2(xw[a].z), asH2(bw[p].z), acc[a][p]);
                    acc[a][p] = __hfma2(asH2(xw[a].w), asH2(bw[p].w), acc[a][p]);
                }
        }

        // epilogue: biased key = bn2b - 2*dot (half2); pack (halfbits<<16|loc)
        unsigned lp[4];
        {
            unsigned loc0 = (unsigned)(tl * 128 + j * 2);
            #pragma unroll
            for (int p = 0; p < 4; p++)
                lp[p] = (loc0 + p * 32) * 0x00010001u + 0x00010000u;
        }
        #pragma unroll
        for (int a = 0; a < 4; a++) {
            #pragma unroll
            for (int p = 0; p < 4; p++) {
                __half2 key2 = __hfma2(m2, acc[a][p], bnb[p]);
                unsigned cmpv = *reinterpret_cast<unsigned*>(&key2);
                unsigned u0 = __byte_perm(cmpv, lp[p], 0x1054);
                unsigned u1 = __byte_perm(cmpv, lp[p], 0x3276);
                if (u0 < tk[a][10]) bubble11(tk[a], u0);
                if (u1 < tk[a][10]) bubble11(tk[a], u1);
            }
        }
        s_cur = (s_cur == 2) ? 0 : s_cur + 1;
    }

    // block merge: 16 j-threads per row -> per-(row,split) top-11
    __syncthreads();
    unsigned* csh = (unsigned*)smem_raw;   // [64][16][11]
    #pragma unroll
    for (int a = 0; a < 4; a++) {
        int base = ((i + a * 16) * 16 + j) * KK;
        #pragma unroll
        for (int k = 0; k < KK; k++) csh[base + k] = tk[a][k];
    }
    __syncthreads();

    if (tid < BX) {
        const unsigned* src = csh + tid * (16 * KK);
        unsigned best[KK];
        #pragma unroll
        for (int k = 0; k < KK; k++) best[k] = 0xFFFFFFFFu;
        for (int s = 0; s < 16 * KK; s++) {
            unsigned v = src[s];
            if (v < best[10]) bubble11(best, v);
        }
        unsigned* dst = g_cand + ((size_t)(xblock + tid) * SPLITS + split) * KK;
        #pragma unroll
        for (int k = 0; k < KK; k++) dst[k] = best[k];
    }
}

// ---------------- kernel 3: exact fp32 recompute + final reduction ----------
__global__ void __launch_bounds__(128)
finalize_kernel(const float* __restrict__ x, const float* __restrict__ buf,
                float* __restrict__ out) {
    const int row = blockIdx.x;
    const int tid = threadIdx.x;
    __shared__ float4 xr[16];
    __shared__ float sd2[SPLITS * KK];

    if (tid < 16)
        xr[tid] = reinterpret_cast<const float4*>(x + (size_t)row * D_DIM)[tid];
    __syncthreads();

    if (tid < SPLITS * KK) {
        unsigned cand = g_cand[(size_t)row * SPLITS * KK + tid];
        int split = tid / KK;
        int loc = (int)(cand & 0xFFFFu);
        long gidx = (long)split * (TPS * 128) + loc;
        if (gidx >= M_BUF) gidx = M_BUF - 1;   // safety (unreachable)
        const float4* b4 = reinterpret_cast<const float4*>(buf + gidx * D_DIM);
        float s = 0.f;
        #pragma unroll
        for (int q = 0; q < 16; q++) {
            float4 bv = b4[q], xv = xr[q];
            float d0 = xv.x - bv.x, d1 = xv.y - bv.y;
            float d2 = xv.z - bv.z, d3 = xv.w - bv.w;
            s += d0 * d0 + d1 * d1 + d2 * d2 + d3 * d3;
        }
        sd2[tid] = s;
    }
    __syncthreads();

    if (tid == 0) {
        float best[KK];
        float thrv = FLT_MAX; int mi = 0;
        #pragma unroll
        for (int k = 0; k < KK; k++) best[k] = FLT_MAX;
        for (int s = 0; s < SPLITS * KK; s++) {
            float v = sd2[s];
            if (v < thrv) {
                best[mi] = v;
                float m = best[0]; int mj = 0;
                #pragma unroll
                for (int q = 1; q < KK; q++)
                    if (best[q] > m) { m = best[q]; mj = q; }
                thrv = m; mi = mj;
            }
        }
        float ssum = 0.f, rmin = FLT_MAX;
        #pragma unroll
        for (int k = 0; k < KK; k++) {
            float r = sqrtf(best[k]);
            ssum += r;
            rmin = fminf(rmin, r);
        }
        out[row] = log1pf((ssum - rmin) * 0.1f);   // drop self-match, mean of 10
    }
}

// ---------------------------------------------------------------------------
extern "C" void kernel_launch(void* const* d_in, const int* in_sizes, int n_in,
                              void* d_out, int out_size) {
    const float* x   = (const float*)d_in[0];
    const float* buf = (const float*)d_in[1];
    if (n_in >= 2 && in_sizes[0] != N_X * D_DIM) {
        const float* t = x; x = buf; buf = t;
    }

    cudaFuncSetAttribute(pbe_h2, cudaFuncAttributeMaxDynamicSharedMemorySize, SMEM_TOTAL);

    int total_warps = M_BUF / 2 + N_X;
    prep_kernel<<<(total_warps * 32 + 255) / 256, 256>>>(x, buf);
    pbe_h2<<<dim3(N_X / BX, SPLITS), 256, SMEM_TOTAL>>>();
    finalize_kernel<<<N_X, 128>>>(x, buf, (float*)d_out);
}

// round 9
// speedup vs baseline: 1.5034x; 1.0090x over previous
#include <cuda_runtime.h>
#include <cuda_fp16.h>
#include <math.h>
#include <float.h>
#include <stdint.h>

// ---------------- problem constants ----------------
#define N_X    2048
#define M_BUF  131072
#define D_DIM  64
#define KK     11                 // keep K+1 smallest
#define SPLITS 9
#define TPS    114                // tiles per split (last split: 112)
#define TILES_TOTAL (M_BUF / 128) // 1024
#define BX     64                 // x rows per CTA
#define KBIAS  128.0f             // key bias so biased keys are positive halfs

// ---------------- device scratch ----------------
// buf pair-interleaved: g_bp[p*64 + k] = half2(buf[2p][k], buf[2p+1][k])
__device__ __half2 g_bp[(size_t)(M_BUF / 2) * D_DIM];
// x duplicated: g_xd[r*64 + k] = half2(x[r][k], x[r][k])
__device__ __half2 g_xd[(size_t)N_X * D_DIM];
// biased pair norms: g_bnp[p] = half2(bn2[2p]+128, bn2[2p+1]+128)
__device__ __half2 g_bnp[M_BUF / 2];
__device__ unsigned g_cand[(size_t)N_X * SPLITS * KK];

// ---------------- helpers ----------------
__device__ __forceinline__ uint32_t smem_u32(const void* p) {
    uint32_t a;
    asm("{ .reg .u64 t; cvta.to.shared.u64 t, %1; cvt.u32.u64 %0, t; }" : "=r"(a) : "l"(p));
    return a;
}
#define CP_ASYNC16(ds, gp) asm volatile("cp.async.cg.shared.global [%0], [%1], 16;" :: "r"(ds), "l"(gp))
#define CP_COMMIT() asm volatile("cp.async.commit_group;" ::: "memory")
#define CP_WAIT(n)  asm volatile("cp.async.wait_group %0;" :: "n"(n) : "memory")

__device__ __forceinline__ __half2 asH2(unsigned u) { return *reinterpret_cast<__half2*>(&u); }

// sorted ascending insert; v expected <= tk[10] ordering-wise
__device__ __forceinline__ void bubble11(unsigned tk[KK], unsigned v) {
    tk[10] = v;
    #pragma unroll
    for (int s = 10; s >= 1; s--) {
        unsigned lo = min(tk[s - 1], tk[s]);
        unsigned hi = max(tk[s - 1], tk[s]);
        tk[s - 1] = lo; tk[s] = hi;
    }
}

// ---------------- kernel 1: fp16 pack + biased pair norms ----------------
__global__ void prep_kernel(const float* __restrict__ x, const float* __restrict__ buf) {
    int gw = (blockIdx.x * blockDim.x + threadIdx.x) >> 5;
    int lane = threadIdx.x & 31;
    const int NPAIR = M_BUF / 2;
    if (gw >= NPAIR + N_X) return;
    if (gw < NPAIR) {
        const float2 v0 = reinterpret_cast<const float2*>(buf + (size_t)(2 * gw) * D_DIM)[lane];
        const float2 v1 = reinterpret_cast<const float2*>(buf + (size_t)(2 * gw + 1) * D_DIM)[lane];
        __half2* dst = g_bp + (size_t)gw * D_DIM;
        dst[2 * lane]     = __floats2half2_rn(v0.x, v1.x);
        dst[2 * lane + 1] = __floats2half2_rn(v0.y, v1.y);
        float s0 = v0.x * v0.x + v0.y * v0.y;
        float s1 = v1.x * v1.x + v1.y * v1.y;
        #pragma unroll
        for (int o = 16; o > 0; o >>= 1) {
            s0 += __shfl_xor_sync(0xffffffffu, s0, o);
            s1 += __shfl_xor_sync(0xffffffffu, s1, o);
        }
        if (lane == 0) g_bnp[gw] = __floats2half2_rn(s0 + KBIAS, s1 + KBIAS);
    } else {
        int r = gw - NPAIR;
        const float2 v = reinterpret_cast<const float2*>(x + (size_t)r * D_DIM)[lane];
        __half2* dst = g_xd + (size_t)r * D_DIM;
        dst[2 * lane]     = __floats2half2_rn(v.x, v.x);
        dst[2 * lane + 1] = __floats2half2_rn(v.y, v.y);
    }
}

// ---------------- kernel 2: HFMA2 distances + register top-11 ----------------
// smem: XS [0,16384); B0/B1/B2 @16384+17408*s (64 pairs x 272B);
// BN0/1/2 @68608+256*s. total 69632. merge phase aliases [0,22528).
#define XS_OFF  0
#define BB_OFF  16384
#define BB_STRIDE 17408
#define BN_OFF  68608
#define PROWB   272
#define SMEM_TOTAL 69632

extern __shared__ unsigned char smem_raw[];

__device__ __forceinline__ void prefetch_tile(uint32_t sb, int tile, int sel, int tid) {
    uint32_t boff = BB_OFF + sel * BB_STRIDE;
    const char* src = (const char*)g_bp + (size_t)tile * 16384;
    #pragma unroll
    for (int ii = 0; ii < 4; ii++) {
        int q = tid + 256 * ii;            // 1024 16B chunks
        int prow = q >> 4, c = q & 15;
        CP_ASYNC16(sb + boff + prow * PROWB + c * 16, src + prow * 256 + c * 16);
    }
    if (tid < 16)
        CP_ASYNC16(sb + BN_OFF + sel * 256 + tid * 16,
                   (const char*)g_bnp + (size_t)tile * 256 + tid * 16);
}

__global__ void __launch_bounds__(256, 2)
pbe_h2() {
    const int tid = threadIdx.x;
    const int i = tid >> 3;                // 0..31: x rows {i, i+32}
    const int j = tid & 7;                 // 0..7: pairs {j + 8n, n=0..7}
    const int xblock = blockIdx.x * BX;
    const int split  = blockIdx.y;
    const int tbeg = split * TPS;
    const int tend = min(tbeg + TPS, TILES_TOTAL);

    uint32_t sb = smem_u32(smem_raw);

    // x tile: linear 16KB copy from g_xd
    {
        const char* src = (const char*)g_xd + (size_t)xblock * 256;
        #pragma unroll
        for (int ii = 0; ii < 4; ii++) {
            int q = tid + 256 * ii;
            CP_ASYNC16(sb + XS_OFF + q * 16, src + q * 16);
        }
    }
    prefetch_tile(sb, tbeg, 0, tid);
    CP_COMMIT();
    prefetch_tile(sb, tbeg + 1, 1, tid);
    CP_COMMIT();

    unsigned tk[2][KK];
    #pragma unroll
    for (int a = 0; a < 2; a++)
        #pragma unroll
        for (int k = 0; k < KK; k++) tk[a][k] = 0xFFFFFFFFu;
    unsigned thr16_0 = 0xFFFFu, thr16_1 = 0xFFFFu;   // tk[a][10] >> 16

    const __half2 m2 = __float2half2_rn(-2.0f);

    int s_cur = 0;
    for (int t = tbeg; t < tend; t++) {
        const int tl = t - tbeg;
        CP_WAIT(1);                        // tile t resident
        __syncthreads();                   // all warps done with buf s_cur's previous use
        {
            int s_nxt = s_cur + 2; if (s_nxt >= 3) s_nxt -= 3;
            if (t + 2 < tend) prefetch_tile(sb, t + 2, s_nxt, tid);
            CP_COMMIT();
        }

        const unsigned char* bt = smem_raw + BB_OFF + s_cur * BB_STRIDE;
        const __half2* bnp = (const __half2*)(smem_raw + BN_OFF + s_cur * 256);

        unsigned bnb[8];
        #pragma unroll
        for (int n = 0; n < 8; n++) {
            __half2 h = bnp[j + n * 8];
            bnb[n] = *reinterpret_cast<unsigned*>(&h);
        }

        __half2 acc[2][8];
        #pragma unroll
        for (int a = 0; a < 2; a++)
            #pragma unroll
            for (int n = 0; n < 8; n++) acc[a][n] = __float2half2_rn(0.f);

        #pragma unroll
        for (int cp = 0; cp < 16; cp++) {
            uint4 xw0 = *(const uint4*)(smem_raw + XS_OFF + i * 256 + cp * 16);
            uint4 xw1 = *(const uint4*)(smem_raw + XS_OFF + (i + 32) * 256 + cp * 16);
            // first half of pairs
            {
                uint4 bw[4];
                #pragma unroll
                for (int n = 0; n < 4; n++)
                    bw[n] = *(const uint4*)(bt + (j + n * 8) * PROWB + cp * 16);
                #pragma unroll
                for (int n = 0; n < 4; n++) {
                    acc[0][n] = __hfma2(asH2(xw0.x), asH2(bw[n].x), acc[0][n]);
                    acc[0][n] = __hfma2(asH2(xw0.y), asH2(bw[n].y), acc[0][n]);
                    acc[0][n] = __hfma2(asH2(xw0.z), asH2(bw[n].z), acc[0][n]);
                    acc[0][n] = __hfma2(asH2(xw0.w), asH2(bw[n].w), acc[0][n]);
                    acc[1][n] = __hfma2(asH2(xw1.x), asH2(bw[n].x), acc[1][n]);
                    acc[1][n] = __hfma2(asH2(xw1.y), asH2(bw[n].y), acc[1][n]);
                    acc[1][n] = __hfma2(asH2(xw1.z), asH2(bw[n].z), acc[1][n]);
                    acc[1][n] = __hfma2(asH2(xw1.w), asH2(bw[n].w), acc[1][n]);
                }
            }
            // second half of pairs
            {
                uint4 bw[4];
                #pragma unroll
                for (int n = 0; n < 4; n++)
                    bw[n] = *(const uint4*)(bt + (j + (n + 4) * 8) * PROWB + cp * 16);
                #pragma unroll
                for (int n = 0; n < 4; n++) {
                    acc[0][n + 4] = __hfma2(asH2(xw0.x), asH2(bw[n].x), acc[0][n + 4]);
                    acc[0][n + 4] = __hfma2(asH2(xw0.y), asH2(bw[n].y), acc[0][n + 4]);
                    acc[0][n + 4] = __hfma2(asH2(xw0.z), asH2(bw[n].z), acc[0][n + 4]);
                    acc[0][n + 4] = __hfma2(asH2(xw0.w), asH2(bw[n].w), acc[0][n + 4]);
                    acc[1][n + 4] = __hfma2(asH2(xw1.x), asH2(bw[n].x), acc[1][n + 4]);
                    acc[1][n + 4] = __hfma2(asH2(xw1.y), asH2(bw[n].y), acc[1][n + 4]);
                    acc[1][n + 4] = __hfma2(asH2(xw1.z), asH2(bw[n].z), acc[1][n + 4]);
                    acc[1][n + 4] = __hfma2(asH2(xw1.w), asH2(bw[n].w), acc[1][n + 4]);
                }
            }
        }

        // epilogue: key = bn2b - 2*dot (half2); hot path = u16 compares only;
        // PRMT pack + loc computed lazily on insert.
        const unsigned locb = (unsigned)(tl * 128 + j * 2);
        #pragma unroll
        for (int n = 0; n < 8; n++) {
            unsigned lpw = 0;              // computed lazily
            #pragma unroll
            for (int a = 0; a < 2; a++) {
                __half2 key2 = __hfma2(m2, acc[a][n], asH2(bnb[n]));
                unsigned cv = *reinterpret_cast<unsigned*>(&key2);
                unsigned thr = a ? thr16_1 : thr16_0;
                if ((cv & 0xFFFFu) <= thr) {
                    lpw = (locb + n * 16) * 0x00010001u + 0x00010000u;
                    bubble11(tk[a], __byte_perm(cv, lpw, 0x1054));
                    if (a) thr16_1 = tk[1][10] >> 16; else thr16_0 = tk[0][10] >> 16;
                    thr = a ? thr16_1 : thr16_0;
                }
                if ((cv >> 16) <= thr) {
                    lpw = (locb + n * 16) * 0x00010001u + 0x00010000u;
                    bubble11(tk[a], __byte_perm(cv, lpw, 0x3276));
                    if (a) thr16_1 = tk[1][10] >> 16; else thr16_0 = tk[0][10] >> 16;
                }
            }
        }
        s_cur = (s_cur == 2) ? 0 : s_cur + 1;
    }

    // block merge: 8 j-threads per row -> per-(row,split) top-11
    __syncthreads();
    unsigned* csh = (unsigned*)smem_raw;   // [64 rows][8 j][11]
    #pragma unroll
    for (int a = 0; a < 2; a++) {
        int base = ((i + a * 32) * 8 + j) * KK;
        #pragma unroll
        for (int k = 0; k < KK; k++) csh[base + k] = tk[a][k];
    }
    __syncthreads();

    if (tid < BX) {
        const unsigned* src = csh + tid * (8 * KK);
        unsigned best[KK];
        #pragma unroll
        for (int k = 0; k < KK; k++) best[k] = 0xFFFFFFFFu;
        for (int s = 0; s < 8 * KK; s++) {
            unsigned v = src[s];
            if (v < best[10]) bubble11(best, v);
        }
        unsigned* dst = g_cand + ((size_t)(xblock + tid) * SPLITS + split) * KK;
        #pragma unroll
        for (int k = 0; k < KK; k++) dst[k] = best[k];
    }
}

// ---------------- kernel 3: exact fp32 recompute + final reduction ----------
__global__ void __launch_bounds__(128)
finalize_kernel(const float* __restrict__ x, const float* __restrict__ buf,
                float* __restrict__ out) {
    const int row = blockIdx.x;
    const int tid = threadIdx.x;
    __shared__ float4 xr[16];
    __shared__ float sd2[SPLITS * KK];

    if (tid < 16)
        xr[tid] = reinterpret_cast<const float4*>(x + (size_t)row * D_DIM)[tid];
    __syncthreads();

    if (tid < SPLITS * KK) {
        unsigned cand = g_cand[(size_t)row * SPLITS * KK + tid];
        int split = tid / KK;
        int loc = (int)(cand & 0xFFFFu);
        long gidx = (long)split * (TPS * 128) + loc;
        if (gidx >= M_BUF) gidx = M_BUF - 1;   // safety (unreachable)
        const float4* b4 = reinterpret_cast<const float4*>(buf + gidx * D_DIM);
        float s = 0.f;
        #pragma unroll
        for (int q = 0; q < 16; q++) {
            float4 bv = b4[q], xv = xr[q];
            float d0 = xv.x - bv.x, d1 = xv.y - bv.y;
            float d2 = xv.z - bv.z, d3 = xv.w - bv.w;
            s += d0 * d0 + d1 * d1 + d2 * d2 + d3 * d3;
        }
        sd2[tid] = s;
    }
    __syncthreads();

    if (tid == 0) {
        float best[KK];
        float thrv = FLT_MAX; int mi = 0;
        #pragma unroll
        for (int k = 0; k < KK; k++) best[k] = FLT_MAX;
        for (int s = 0; s < SPLITS * KK; s++) {
            float v = sd2[s];
            if (v < thrv) {
                best[mi] = v;
                float m = best[0]; int mj = 0;
                #pragma unroll
                for (int q = 1; q < KK; q++)
                    if (best[q] > m) { m = best[q]; mj = q; }
                thrv = m; mi = mj;
            }
        }
        float ssum = 0.f, rmin = FLT_MAX;
        #pragma unroll
        for (int k = 0; k < KK; k++) {
            float r = sqrtf(best[k]);
            ssum += r;
            rmin = fminf(rmin, r);
        }
        out[row] = log1pf((ssum - rmin) * 0.1f);   // drop self-match, mean of 10
    }
}

// ---------------------------------------------------------------------------
extern "C" void kernel_launch(void* const* d_in, const int* in_sizes, int n_in,
                              void* d_out, int out_size) {
    const float* x   = (const float*)d_in[0];
    const float* buf = (const float*)d_in[1];
    if (n_in >= 2 && in_sizes[0] != N_X * D_DIM) {
        const float* t = x; x = buf; buf = t;
    }

    cudaFuncSetAttribute(pbe_h2, cudaFuncAttributeMaxDynamicSharedMemorySize, SMEM_TOTAL);

    int total_warps = M_BUF / 2 + N_X;
    prep_kernel<<<(total_warps * 32 + 255) / 256, 256>>>(x, buf);
    pbe_h2<<<dim3(N_X / BX, SPLITS), 256, SMEM_TOTAL>>>();
    finalize_kernel<<<N_X, 128>>>(x, buf, (float*)d_out);
}